// round 5
// baseline (speedup 1.0000x reference)
#include <cuda_runtime.h>
#include <cstdint>

// ---------------------------------------------------------------------------
// KAN-Mixer fused kernel (round 2): cp.async double-buffered pipeline,
// single __syncthreads per chunk, mma.sync tf32.
// ---------------------------------------------------------------------------

#define BQ   64
#define PP   196
#define CC   768
#define HSZ  384

#define K1P  1792          // 1764 padded to mult of 64
#define KS1  (K1P/8)       // 224 k8-steps
#define NT1  (HSZ/8)       // 48 n8-tiles
#define NC1  (K1P/32)      // 56 chunks

#define K2   3456          // 3072 + 384
#define KS2  (K2/8)        // 432
#define N2P  224
#define NT2  (N2P/8)       // 28
#define NC2  (K2/32)       // 108 chunks

#define KC   32
#define KSL  (KC/8)        // 4
#define MTILE 64
#define NTHREADS 256

#define L2E 1.4426950408889634f

// fragment-ordered weights: index = ((ks*NT + nt)*32 + t)*2 + r
__device__ float g_W1[(size_t)KS1 * NT1 * 64];   // 2.75 MB
__device__ float g_W2[(size_t)KS2 * NT2 * 64];   // 3.10 MB

static __device__ __forceinline__ float ex2f(float z) {
    float r; asm("ex2.approx.ftz.f32 %0, %1;" : "=f"(r) : "f"(z)); return r;
}
static __device__ __forceinline__ float rcpf(float z) {
    float r; asm("rcp.approx.ftz.f32 %0, %1;" : "=f"(r) : "f"(z)); return r;
}
static __device__ __forceinline__ unsigned tf32r(float v) {
    unsigned u; asm("cvt.rna.tf32.f32 %0, %1;" : "=r"(u) : "f"(v)); return u;
}
static __device__ __forceinline__ float basis_feat(float v, int q) {
    float u = (v + 1.0f) * 3.5f - (float)q;
    float z = fmaxf(-u * u * L2E, -126.0f);
    return ex2f(z);
}
static __device__ __forceinline__ float silu_feat(float v) {
    float z = fminf(fmaxf(-v * L2E, -126.0f), 126.0f);
    return v * rcpf(1.0f + ex2f(z));
}

static __device__ __forceinline__ void mma8(float* d, const uint4& A, const uint2& B) {
    asm volatile(
        "mma.sync.aligned.m16n8k8.row.col.f32.tf32.tf32.f32 "
        "{%0,%1,%2,%3}, {%4,%5,%6,%7}, {%8,%9}, {%0,%1,%2,%3};"
        : "+f"(d[0]), "+f"(d[1]), "+f"(d[2]), "+f"(d[3])
        : "r"(A.x), "r"(A.y), "r"(A.z), "r"(A.w), "r"(B.x), "r"(B.y));
}

static __device__ __forceinline__ void cpasync16(float* dst, const float* src) {
    unsigned s = (unsigned)__cvta_generic_to_shared(dst);
    asm volatile("cp.async.ca.shared.global [%0], [%1], 16;" :: "r"(s), "l"(src));
}
static __device__ __forceinline__ void cp_commit() {
    asm volatile("cp.async.commit_group;" ::: "memory");
}
static __device__ __forceinline__ void cp_wait0() {
    asm volatile("cp.async.wait_group 0;" ::: "memory");
}

// ------------------------- weight prep kernels ------------------------------
__global__ void prep1(const float* __restrict__ sw, const float* __restrict__ bw) {
    int idx = blockIdx.x * blockDim.x + threadIdx.x;
    if (idx >= KS1 * NT1 * 64) return;
    int r = idx & 1, t = (idx >> 1) & 31, tmp = idx >> 6;
    int nt = tmp % NT1, ks = tmp / NT1;
    int n = nt * 8 + (t >> 2);
    int k = ks * 8 + (t & 3) + r * 4;
    float v = 0.0f;
    if (k < 1568)       v = sw[n * 1568 + k];
    else if (k < 1764)  v = bw[n * 196 + (k - 1568)];
    g_W1[idx] = __uint_as_float(tf32r(v));
}

__global__ void prep2(const float* __restrict__ sw, const float* __restrict__ bw) {
    int idx = blockIdx.x * blockDim.x + threadIdx.x;
    if (idx >= KS2 * NT2 * 64) return;
    int r = idx & 1, t = (idx >> 1) & 31, tmp = idx >> 6;
    int nt = tmp % NT2, ks = tmp / NT2;
    int n = nt * 8 + (t >> 2);
    int k = ks * 8 + (t & 3) + r * 4;
    float v = 0.0f;
    if (n < PP) {
        if (k < 3072)      v = sw[n * 3072 + k];
        else               v = bw[n * 384 + (k - 3072)];
    }
    g_W2[idx] = __uint_as_float(tf32r(v));
}

// ------------------------------ main kernel ---------------------------------
// smem layout (floats):
//   [0, 24640)         region0: xs[196][64] during L1, then h[64][385]
//   [24640, 26688)     As0    (2048 floats)
//   [26688, 28736)     As1
//   [28736, 41024)     Bs0    (12288 floats, max chunk = L1's 4ks*48nt*64)
//   [41024, 53312)     Bs1
#define SM_AS0  24640
#define SM_AS1  26688
#define SM_BS0  28736
#define SM_BS1  41024
#define SM_TOT  53312
#define HSTRIDE 385

__global__ void __launch_bounds__(NTHREADS, 1)
kan_main(const float* __restrict__ x, const float* __restrict__ b1v,
         const float* __restrict__ b2v, float* __restrict__ out) {
    extern __shared__ float smem[];
    float* reg0 = smem;
    float* As0  = smem + SM_AS0;
    float* As1  = smem + SM_AS1;
    float* Bs0  = smem + SM_BS0;
    float* Bs1  = smem + SM_BS1;

    const int m0  = blockIdx.x * MTILE;
    const int b   = m0 / CC;
    const int c0  = m0 % CC;
    const int tid = threadIdx.x;
    const int w    = tid >> 5, lane = tid & 31;
    const int mw   = w & 1;
    const int nG   = w >> 1;
    const int g    = lane >> 2, t4 = lane & 3;

    // ---- prefetch L1 chunk 0 weights (overlaps x-slab load) ----
#pragma unroll
    for (int i = 0; i < 12; ++i) {
        int v = tid + i * NTHREADS;
        cpasync16(Bs0 + v * 4, g_W1 + (size_t)v * 4);
    }
    cp_commit();

    // ---- load x slab: xs[p][r] = x[b, p, c0+r] ----
    {
        const float4* xg = reinterpret_cast<const float4*>(x + (size_t)b * PP * CC + c0);
        float4* xs4 = reinterpret_cast<float4*>(reg0);
        for (int i = tid; i < PP * 16; i += NTHREADS) {
            int p = i >> 4, r4 = i & 15;
            xs4[p * 16 + r4] = xg[p * (CC / 4) + r4];
        }
    }
    __syncthreads();

    float acc[2][12][4];
#pragma unroll
    for (int mi = 0; mi < 2; ++mi)
#pragma unroll
        for (int nti = 0; nti < 12; ++nti)
#pragma unroll
            for (int ci = 0; ci < 4; ++ci) acc[mi][nti][ci] = 0.0f;

    // ============================ layer 1 ============================
    for (int kc = 0; kc < NC1; ++kc) {
        const int k0 = kc * KC;
        float* Asc = (kc & 1) ? As1 : As0;
        const float* Bsc = (kc & 1) ? Bs1 : Bs0;

        // generate feature chunk into fragment layout (buffer kc&1)
#pragma unroll
        for (int i = 0; i < 8; ++i) {
            int idx = tid + i * NTHREADS;      // idx = kL*64 + r
            int r  = idx & 63, kL = idx >> 6;
            int k  = k0 + kL;
            float val = 0.0f;
            if (k < 1568) {
                val = basis_feat(reg0[(k >> 3) * 64 + r], k & 7);
            } else if (k < 1764) {
                val = silu_feat(reg0[(k - 1568) * 64 + r]);
            }
            int mt = r >> 4, rl = r & 15, ksL = kL >> 3, kk = kL & 7;
            int t = ((rl & 7) << 2) | (kk & 3);
            int a = ((kk >> 2) << 1) | (rl >> 3);
            Asc[(((mt << 2) + ksL) << 7) + (t << 2) + a] = __uint_as_float(tf32r(val));
        }
        cp_wait0();
        __syncthreads();   // single barrier per chunk

        // prefetch next weight chunk into the other buffer
        if (kc + 1 < NC1) {
            float* Bnx = (kc & 1) ? Bs0 : Bs1;
            const float* wsrc = g_W1 + (size_t)((k0 + KC) / 8) * NT1 * 64;
#pragma unroll
            for (int i = 0; i < 12; ++i) {
                int v = tid + i * NTHREADS;
                cpasync16(Bnx + v * 4, wsrc + (size_t)v * 4);
            }
            cp_commit();
        } else {
            // last L1 chunk (kc=55, odd): prefetch L2 chunk 0 into Bs0
            float* Bnx = Bs0;
#pragma unroll
            for (int i = 0; i < 7; ++i) {
                int v = tid + i * NTHREADS;
                cpasync16(Bnx + v * 4, g_W2 + (size_t)v * 4);
            }
            cp_commit();
        }

        // MMA
#pragma unroll
        for (int ksL = 0; ksL < KSL; ++ksL) {
            uint4 Af[2];
#pragma unroll
            for (int mi = 0; mi < 2; ++mi) {
                int mt = mw * 2 + mi;
                Af[mi] = reinterpret_cast<const uint4*>(Asc)[(mt * 4 + ksL) * 32 + lane];
            }
#pragma unroll
            for (int nti = 0; nti < 12; ++nti) {
                int nt = nG * 12 + nti;
                uint2 Bf = reinterpret_cast<const uint2*>(Bsc)[(ksL * NT1 + nt) * 32 + lane];
#pragma unroll
                for (int mi = 0; mi < 2; ++mi) mma8(acc[mi][nti], Af[mi], Bf);
            }
        }
    }

    // ---- h epilogue: h[row][col] = acc + b1[col], stored in reg0 ----
    // (MMA stragglers don't read reg0; all feature reads of xs finished
    //  before the last chunk's barrier, so writing reg0 here is safe.)
#pragma unroll
    for (int mi = 0; mi < 2; ++mi)
#pragma unroll
        for (int nti = 0; nti < 12; ++nti)
#pragma unroll
            for (int ci = 0; ci < 4; ++ci) {
                int row = mw * 32 + mi * 16 + g + 8 * (ci >> 1);
                int col = nG * 96 + nti * 8 + 2 * t4 + (ci & 1);
                reg0[row * HSTRIDE + col] = acc[mi][nti][ci] + b1v[col];
            }
    __syncthreads();

    // ============================ layer 2 ============================
#pragma unroll
    for (int mi = 0; mi < 2; ++mi)
#pragma unroll
        for (int nti = 0; nti < 7; ++nti)
#pragma unroll
            for (int ci = 0; ci < 4; ++ci) acc[mi][nti][ci] = 0.0f;

    for (int kc = 0; kc < NC2; ++kc) {
        const int k0 = kc * KC;
        float* Asc = (kc & 1) ? As1 : As0;
        const float* Bsc = (kc & 1) ? Bs1 : Bs0;

#pragma unroll
        for (int i = 0; i < 8; ++i) {
            int idx = tid + i * NTHREADS;
            int r  = idx & 63, kL = idx >> 6;
            int k  = k0 + kL;
            float val;
            if (k < 3072) {
                val = basis_feat(reg0[r * HSTRIDE + (k >> 3)], k & 7);
            } else {
                val = silu_feat(reg0[r * HSTRIDE + (k - 3072)]);
            }
            int mt = r >> 4, rl = r & 15, ksL = kL >> 3, kk = kL & 7;
            int t = ((rl & 7) << 2) | (kk & 3);
            int a = ((kk >> 2) << 1) | (rl >> 3);
            Asc[(((mt << 2) + ksL) << 7) + (t << 2) + a] = __uint_as_float(tf32r(val));
        }
        cp_wait0();
        __syncthreads();

        if (kc + 1 < NC2) {
            float* Bnx = (kc & 1) ? Bs0 : Bs1;
            const float* wsrc = g_W2 + (size_t)((k0 + KC) / 8) * NT2 * 64;
#pragma unroll
            for (int i = 0; i < 7; ++i) {
                int v = tid + i * NTHREADS;
                cpasync16(Bnx + v * 4, wsrc + (size_t)v * 4);
            }
            cp_commit();
        }

#pragma unroll
        for (int ksL = 0; ksL < KSL; ++ksL) {
            uint4 Af[2];
#pragma unroll
            for (int mi = 0; mi < 2; ++mi) {
                int mt = mw * 2 + mi;
                Af[mi] = reinterpret_cast<const uint4*>(Asc)[(mt * 4 + ksL) * 32 + lane];
            }
#pragma unroll
            for (int nti = 0; nti < 7; ++nti) {
                int nt = nG * 7 + nti;
                uint2 Bf = reinterpret_cast<const uint2*>(Bsc)[(ksL * NT2 + nt) * 32 + lane];
#pragma unroll
                for (int mi = 0; mi < 2; ++mi) mma8(acc[mi][nti], Af[mi], Bf);
            }
        }
    }

    // ---- epilogue: out[b,p,c0+row] = acc + b2[p] + x[b,p,c0+row] ----
#pragma unroll
    for (int mi = 0; mi < 2; ++mi)
#pragma unroll
        for (int nti = 0; nti < 7; ++nti)
#pragma unroll
            for (int ci = 0; ci < 4; ++ci) {
                int row = mw * 32 + mi * 16 + g + 8 * (ci >> 1);
                int p   = nG * 56 + nti * 8 + 2 * t4 + (ci & 1);
                if (p < PP) {
                    size_t ga = ((size_t)b * PP + p) * CC + c0 + row;
                    out[ga] = acc[mi][nti][ci] + b2v[p] + x[ga];
                }
            }
}

// ------------------------------ launcher ------------------------------------
extern "C" void kernel_launch(void* const* d_in, const int* in_sizes, int n_in,
                              void* d_out, int out_size) {
    (void)in_sizes; (void)n_in; (void)out_size;
    const float* x  = (const float*)d_in[0];
    const float* s1 = (const float*)d_in[1];
    const float* w1 = (const float*)d_in[2];
    const float* b1 = (const float*)d_in[3];
    const float* s2 = (const float*)d_in[4];
    const float* w2 = (const float*)d_in[5];
    const float* b2 = (const float*)d_in[6];
    float* out = (float*)d_out;

    prep1<<<(KS1 * NT1 * 64 + 255) / 256, 256>>>(s1, w1);
    prep2<<<(KS2 * NT2 * 64 + 255) / 256, 256>>>(s2, w2);

    const int smemBytes = SM_TOT * 4;   // 213,248 B
    cudaFuncSetAttribute(kan_main, cudaFuncAttributeMaxDynamicSharedMemorySize, smemBytes);
    kan_main<<<(BQ * CC) / MTILE, NTHREADS, smemBytes>>>(x, b1, b2, out);
}

// round 7
// speedup vs baseline: 3.2160x; 3.2160x over previous
#include <cuda_runtime.h>
#include <cuda_fp16.h>
#include <cstdint>

// ---------------------------------------------------------------------------
// KAN-Mixer fused kernel (round 4): fp16 mma.sync m16n8k16, fp32 accumulate,
// 2 CTAs/SM, cp.async double-buffered weights, h stored fp16 in smem.
// ---------------------------------------------------------------------------

#define PP   196
#define CC   768
#define HSZ  384

#define K1P  1792          // 1764 padded
#define NT1  48            // n8 tiles layer1
#define NC1  56            // chunks of 32
#define K2   3456
#define NT2  28            // n8 tiles layer2 (224 padded)
#define NC2  108

#define MTILE 64
#define NTH  256
#define L2E  1.4426950408889634f

// fragment-ordered packed fp16 weights (uint = half2):
// index = (ks16*NT + nt)*64 + lane*2 + r ; half2 = {W[n][k], W[n][k+1]},
// n = nt*8 + lane/4, k = ks16*16 + r*8 + (lane%4)*2
__device__ unsigned g_W1[112u * 48u * 64u];   // 1.31 MB
__device__ unsigned g_W2[216u * 28u * 64u];   // 1.48 MB

// ----------------------------- helpers --------------------------------------
static __device__ __forceinline__ float ex2f(float z) {
    float r; asm("ex2.approx.ftz.f32 %0, %1;" : "=f"(r) : "f"(z)); return r;
}
static __device__ __forceinline__ float rcpf(float z) {
    float r; asm("rcp.approx.ftz.f32 %0, %1;" : "=f"(r) : "f"(z)); return r;
}
static __device__ __forceinline__ float basis_feat(float v, int q) {
    float u = (v + 1.0f) * 3.5f - (float)q;
    float z = fmaxf(-u * u * L2E, -126.0f);
    return ex2f(z);
}
static __device__ __forceinline__ float silu_feat(float v) {
    float z = fminf(fmaxf(-v * L2E, -126.0f), 126.0f);
    return v * rcpf(1.0f + ex2f(z));
}
static __device__ __forceinline__ unsigned h2pack(float a, float b) {
    __half2 h = __floats2half2_rn(a, b);
    return *reinterpret_cast<unsigned*>(&h);
}
static __device__ __forceinline__ void mma16(float* d, const uint4& A, const uint2& B) {
    asm volatile(
        "mma.sync.aligned.m16n8k16.row.col.f32.f16.f16.f32 "
        "{%0,%1,%2,%3}, {%4,%5,%6,%7}, {%8,%9}, {%0,%1,%2,%3};"
        : "+f"(d[0]), "+f"(d[1]), "+f"(d[2]), "+f"(d[3])
        : "r"(A.x), "r"(A.y), "r"(A.z), "r"(A.w), "r"(B.x), "r"(B.y));
}
static __device__ __forceinline__ void cpasync16(void* dst, const void* src) {
    unsigned s = (unsigned)__cvta_generic_to_shared(dst);
    asm volatile("cp.async.cg.shared.global [%0], [%1], 16;" :: "r"(s), "l"(src));
}
static __device__ __forceinline__ void cp_commit() {
    asm volatile("cp.async.commit_group;" ::: "memory");
}
static __device__ __forceinline__ void cp_wait0() {
    asm volatile("cp.async.wait_group 0;" ::: "memory");
}

// ------------------------- weight prep kernels ------------------------------
__global__ void prep1(const float* __restrict__ sw, const float* __restrict__ bw) {
    unsigned idx = blockIdx.x * blockDim.x + threadIdx.x;
    if (idx >= 112u * 48u * 64u) return;
    unsigned r = idx & 1, lane = (idx >> 1) & 31;
    unsigned nt = (idx >> 6) % 48, ks = (idx >> 6) / 48;
    unsigned n = nt * 8 + (lane >> 2);
    unsigned k = ks * 16 + r * 8 + (lane & 3) * 2;
    float v0 = 0.0f, v1 = 0.0f;
    if (k < 1568)       v0 = sw[n * 1568 + k];
    else if (k < 1764)  v0 = bw[n * 196 + (k - 1568)];
    unsigned k1 = k + 1;
    if (k1 < 1568)      v1 = sw[n * 1568 + k1];
    else if (k1 < 1764) v1 = bw[n * 196 + (k1 - 1568)];
    g_W1[idx] = h2pack(v0, v1);
}

__global__ void prep2(const float* __restrict__ sw, const float* __restrict__ bw) {
    unsigned idx = blockIdx.x * blockDim.x + threadIdx.x;
    if (idx >= 216u * 28u * 64u) return;
    unsigned r = idx & 1, lane = (idx >> 1) & 31;
    unsigned nt = (idx >> 6) % 28, ks = (idx >> 6) / 28;
    unsigned n = nt * 8 + (lane >> 2);
    unsigned k = ks * 16 + r * 8 + (lane & 3) * 2;
    float v0 = 0.0f, v1 = 0.0f;
    if (n < PP) {
        if (k < 3072)       v0 = sw[n * 3072 + k];
        else                v0 = bw[n * 384 + (k - 3072)];
        unsigned k1 = k + 1;
        if (k1 < 3072)      v1 = sw[n * 3072 + k1];
        else                v1 = bw[n * 384 + (k1 - 3072)];
    }
    g_W2[idx] = h2pack(v0, v1);
}

// ------------------------------ main kernel ---------------------------------
// smem (float units):
//   [0,384)        b1s
//   [384,608)      b2s
//   [640,13184)    region0: xs fp32 [196][64]  (L1) / h fp16 [64][392] (L2)
//   [13184,14208)  As0 (1024 f = 256 uint4 fragments)
//   [14208,15232)  As1
//   [15232,21376)  Bs0 (6144 f = L1 chunk 6144 uints)
//   [21376,27520)  Bs1
#define SM_B1   0
#define SM_B2   384
#define SM_R0   640
#define SM_A0   13184
#define SM_A1   14208
#define SM_BS0  15232
#define SM_BS1  21376
#define SM_TOTF 27520
#define HST     392        // h stride in halfs

__global__ void __launch_bounds__(NTH, 2)
kan_main(const float* __restrict__ x, const float* __restrict__ b1,
         const float* __restrict__ b2, float* __restrict__ out) {
    extern __shared__ float smem[];
    float*  b1s = smem + SM_B1;
    float*  b2s = smem + SM_B2;
    float*  xs  = smem + SM_R0;                       // fp32 [196][64]
    __half* hs  = reinterpret_cast<__half*>(smem + SM_R0);  // fp16 [64][392]
    unsigned* Bsu[2] = { reinterpret_cast<unsigned*>(smem + SM_BS0),
                         reinterpret_cast<unsigned*>(smem + SM_BS1) };
    uint4* As4[2] = { reinterpret_cast<uint4*>(smem + SM_A0),
                      reinterpret_cast<uint4*>(smem + SM_A1) };

    const int tid = threadIdx.x;
    const int w = tid >> 5, lane = tid & 31;
    const int mw = w & 1;           // row half
    const int nG = w >> 1;          // col group 0..3
    const int g = lane >> 2, c4 = lane & 3;
    // feature-gen decomposition (per-thread fragment word)
    const int fmt = tid >> 6, fks = (tid >> 5) & 1;
    const int fg = g, fc4 = c4;
    const int fr0 = fmt * 16 + fg, fr1 = fr0 + 8;

    const int m0 = blockIdx.x * MTILE;
    const int b  = m0 / CC;
    const int c0 = m0 % CC;

    // ---- prefetch L1 chunk 0 weights ----
#pragma unroll
    for (int i = 0; i < 6; ++i) {
        int v = tid + i * NTH;
        cpasync16(Bsu[0] + v * 4, g_W1 + (size_t)v * 4);
    }
    cp_commit();

    // ---- load x slab + biases ----
    {
        const float4* xg = reinterpret_cast<const float4*>(x + (size_t)b * PP * CC + c0);
        float4* xs4 = reinterpret_cast<float4*>(xs);
        for (int i = tid; i < PP * 16; i += NTH) {
            int p = i >> 4, r4 = i & 15;
            xs4[p * 16 + r4] = xg[p * (CC / 4) + r4];
        }
        for (int i = tid; i < HSZ; i += NTH) b1s[i] = b1[i];
        if (tid < 224) b2s[tid] = (tid < PP) ? b2[tid] : 0.0f;
    }
    __syncthreads();

    float acc[2][12][4];
#pragma unroll
    for (int mi = 0; mi < 2; ++mi)
#pragma unroll
        for (int nti = 0; nti < 12; ++nti)
#pragma unroll
            for (int ci = 0; ci < 4; ++ci) acc[mi][nti][ci] = 0.0f;

    // ============================ layer 1 ============================
    for (int kc = 0; kc < NC1; ++kc) {
        const int k0 = kc * 32;
        const int bi = kc & 1;

        // generate A fragment word (8 fp16 features) per thread
        {
            const int kb0 = k0 + fks * 16 + fc4 * 2;   // k for a0/a1 pair
            const int kb1 = kb0 + 8;                   // k for a2/a3 pair
            uint4 aw;
            if (kc < 49) {     // pure basis region: (kb,kb+1) share p, q even
                const int p0 = kb0 >> 3, q0 = kb0 & 7;
                const int p1 = kb1 >> 3, q1 = kb1 & 7;
                float x00 = xs[p0 * 64 + fr0], x01 = xs[p0 * 64 + fr1];
                float x10 = xs[p1 * 64 + fr0], x11 = xs[p1 * 64 + fr1];
                aw.x = h2pack(basis_feat(x00, q0), basis_feat(x00, q0 + 1));
                aw.y = h2pack(basis_feat(x01, q0), basis_feat(x01, q0 + 1));
                aw.z = h2pack(basis_feat(x10, q1), basis_feat(x10, q1 + 1));
                aw.w = h2pack(basis_feat(x11, q1), basis_feat(x11, q1 + 1));
            } else {           // silu / pad region, each k -> its own p
                float f00 = (kb0 < 1764) ? silu_feat(xs[(kb0 - 1568) * 64 + fr0]) : 0.0f;
                float f01 = (kb0 + 1 < 1764) ? silu_feat(xs[(kb0 - 1567) * 64 + fr0]) : 0.0f;
                float f02 = (kb0 < 1764) ? silu_feat(xs[(kb0 - 1568) * 64 + fr1]) : 0.0f;
                float f03 = (kb0 + 1 < 1764) ? silu_feat(xs[(kb0 - 1567) * 64 + fr1]) : 0.0f;
                float f10 = (kb1 < 1764) ? silu_feat(xs[(kb1 - 1568) * 64 + fr0]) : 0.0f;
                float f11 = (kb1 + 1 < 1764) ? silu_feat(xs[(kb1 - 1567) * 64 + fr0]) : 0.0f;
                float f12 = (kb1 < 1764) ? silu_feat(xs[(kb1 - 1568) * 64 + fr1]) : 0.0f;
                float f13 = (kb1 + 1 < 1764) ? silu_feat(xs[(kb1 - 1567) * 64 + fr1]) : 0.0f;
                aw.x = h2pack(f00, f01);
                aw.y = h2pack(f02, f03);
                aw.z = h2pack(f10, f11);
                aw.w = h2pack(f12, f13);
            }
            As4[bi][tid] = aw;
        }
        cp_wait0();
        __syncthreads();

        // prefetch next weight chunk
        if (kc + 1 < NC1) {
            const unsigned* src = g_W1 + (size_t)(kc + 1) * 6144;
            unsigned* dst = Bsu[bi ^ 1];
#pragma unroll
            for (int i = 0; i < 6; ++i) {
                int v = tid + i * NTH;
                cpasync16(dst + v * 4, src + (size_t)v * 4);
            }
            cp_commit();
        } else {
            // last L1 chunk (kc=55, odd) -> prefetch L2 chunk 0 into Bs0
            unsigned* dst = Bsu[0];
#pragma unroll
            for (int i = 0; i < 4; ++i) {
                int v = tid + i * NTH;
                if (v < 896) cpasync16(dst + v * 4, g_W2 + (size_t)v * 4);
            }
            cp_commit();
        }

        // MMA
        const uint2* Bs2 = reinterpret_cast<const uint2*>(Bsu[bi]);
#pragma unroll
        for (int ks = 0; ks < 2; ++ks) {
            uint4 Af[2];
#pragma unroll
            for (int mi = 0; mi < 2; ++mi)
                Af[mi] = As4[bi][((mw * 2 + mi) * 2 + ks) * 32 + lane];
#pragma unroll
            for (int nti = 0; nti < 12; ++nti) {
                int nt = nG * 12 + nti;
                uint2 Bf = Bs2[(ks * NT1 + nt) * 32 + lane];
#pragma unroll
                for (int mi = 0; mi < 2; ++mi) mma16(acc[mi][nti], Af[mi], Bf);
            }
        }
    }

    // ---- h epilogue: hs[row][col] = fp16(acc + b1[col]) ----
    // (all xs reads finished before last chunk's barrier; safe to overwrite)
#pragma unroll
    for (int mi = 0; mi < 2; ++mi)
#pragma unroll
        for (int nti = 0; nti < 12; ++nti)
#pragma unroll
            for (int ci = 0; ci < 4; ++ci) {
                int row = mw * 32 + mi * 16 + g + 8 * (ci >> 1);
                int col = nG * 96 + nti * 8 + 2 * c4 + (ci & 1);
                hs[row * HST + col] = __float2half(acc[mi][nti][ci] + b1s[col]);
            }
    __syncthreads();

    // ============================ layer 2 ============================
#pragma unroll
    for (int mi = 0; mi < 2; ++mi)
#pragma unroll
        for (int nti = 0; nti < 7; ++nti)
#pragma unroll
            for (int ci = 0; ci < 4; ++ci) acc[mi][nti][ci] = 0.0f;

    for (int kc = 0; kc < NC2; ++kc) {
        const int k0 = kc * 32;
        const int bi = kc & 1;

        {
            const int kb0 = k0 + fks * 16 + fc4 * 2;
            const int kb1 = kb0 + 8;
            uint4 aw;
            if (kc < 96) {     // basis over h
                const int j0 = kb0 >> 3, q0 = kb0 & 7;
                const int j1 = kb1 >> 3, q1 = kb1 & 7;
                float h00 = __half2float(hs[fr0 * HST + j0]);
                float h01 = __half2float(hs[fr1 * HST + j0]);
                float h10 = __half2float(hs[fr0 * HST + j1]);
                float h11 = __half2float(hs[fr1 * HST + j1]);
                aw.x = h2pack(basis_feat(h00, q0), basis_feat(h00, q0 + 1));
                aw.y = h2pack(basis_feat(h01, q0), basis_feat(h01, q0 + 1));
                aw.z = h2pack(basis_feat(h10, q1), basis_feat(h10, q1 + 1));
                aw.w = h2pack(basis_feat(h11, q1), basis_feat(h11, q1 + 1));
            } else {           // silu over h, k in [3072, 3456)
                const int j00 = kb0 - 3072, j10 = kb1 - 3072;
                float f00 = silu_feat(__half2float(hs[fr0 * HST + j00]));
                float f01 = silu_feat(__half2float(hs[fr0 * HST + j00 + 1]));
                float f02 = silu_feat(__half2float(hs[fr1 * HST + j00]));
                float f03 = silu_feat(__half2float(hs[fr1 * HST + j00 + 1]));
                float f10 = silu_feat(__half2float(hs[fr0 * HST + j10]));
                float f11 = silu_feat(__half2float(hs[fr0 * HST + j10 + 1]));
                float f12 = silu_feat(__half2float(hs[fr1 * HST + j10]));
                float f13 = silu_feat(__half2float(hs[fr1 * HST + j10 + 1]));
                aw.x = h2pack(f00, f01);
                aw.y = h2pack(f02, f03);
                aw.z = h2pack(f10, f11);
                aw.w = h2pack(f12, f13);
            }
            As4[bi][tid] = aw;
        }
        cp_wait0();
        __syncthreads();

        if (kc + 1 < NC2) {
            const unsigned* src = g_W2 + (size_t)(kc + 1) * 3584;
            unsigned* dst = Bsu[bi ^ 1];
#pragma unroll
            for (int i = 0; i < 4; ++i) {
                int v = tid + i * NTH;
                if (v < 896) cpasync16(dst + v * 4, src + (size_t)v * 4);
            }
            cp_commit();
        }

        const uint2* Bs2 = reinterpret_cast<const uint2*>(Bsu[bi]);
#pragma unroll
        for (int ks = 0; ks < 2; ++ks) {
            uint4 Af[2];
#pragma unroll
            for (int mi = 0; mi < 2; ++mi)
                Af[mi] = As4[bi][((mw * 2 + mi) * 2 + ks) * 32 + lane];
#pragma unroll
            for (int nti = 0; nti < 7; ++nti) {
                int nt = nG * 7 + nti;
                uint2 Bf = Bs2[(ks * NT2 + nt) * 32 + lane];
#pragma unroll
                for (int mi = 0; mi < 2; ++mi) mma16(acc[mi][nti], Af[mi], Bf);
            }
        }
    }

    // ---- epilogue: out = acc + b2[p] + x (x re-read from gmem) ----
#pragma unroll
    for (int mi = 0; mi < 2; ++mi)
#pragma unroll
        for (int nti = 0; nti < 7; ++nti)
#pragma unroll
            for (int ci = 0; ci < 4; ++ci) {
                int row = mw * 32 + mi * 16 + g + 8 * (ci >> 1);
                int p   = nG * 56 + nti * 8 + 2 * c4 + (ci & 1);
                if (p < PP) {
                    size_t ga = ((size_t)b * PP + p) * CC + c0 + row;
                    out[ga] = acc[mi][nti][ci] + b2s[p] + x[ga];
                }
            }
}

// ------------------------------ launcher ------------------------------------
extern "C" void kernel_launch(void* const* d_in, const int* in_sizes, int n_in,
                              void* d_out, int out_size) {
    (void)in_sizes; (void)n_in; (void)out_size;
    const float* x  = (const float*)d_in[0];
    const float* s1 = (const float*)d_in[1];
    const float* w1 = (const float*)d_in[2];
    const float* b1 = (const float*)d_in[3];
    const float* s2 = (const float*)d_in[4];
    const float* w2 = (const float*)d_in[5];
    const float* b2 = (const float*)d_in[6];
    float* out = (float*)d_out;

    prep1<<<(112u * 48u * 64u + 255) / 256, 256>>>(s1, w1);
    prep2<<<(216u * 28u * 64u + 255) / 256, 256>>>(s2, w2);

    const int smemBytes = SM_TOTF * 4;   // 110,080 B -> 2 CTAs/SM
    cudaFuncSetAttribute(kan_main, cudaFuncAttributeMaxDynamicSharedMemorySize, smemBytes);
    kan_main<<<(64 * CC) / MTILE, NTH, smemBytes>>>(x, b1, b2, out);
}